// round 2
// baseline (speedup 1.0000x reference)
#include <cuda_runtime.h>
#include <math.h>

#define SGRID 14
#define L_COORD 5.0f
#define L_NOOBJ 0.5f
#define NBATCH 4096
#define CELLS (NBATCH * SGRID * SGRID)  /* 802816 */
#define TPB 128

// accumulators: 0=cls 1=noobj 2=reg0 3=reg1 4=c0sum 5=c0sq 6=c1sum 7=c1sq 8=nobj
__device__ double g_acc[9];
__device__ int g_idx;
__device__ int g_mode;   // 0=uint8/bool, 1=int32, 2=float32

__global__ void yolo_init_kernel(const unsigned int* __restrict__ objraw) {
    int t = threadIdx.x;
    if (t < 9) g_acc[t] = 0.0;
    if (t == 9) g_idx = -1;
    if (t == 0) {
        // Probe has_object_map dtype. Cell (0,0,0) is guaranteed True.
        unsigned int w0 = objraw[0];
        int mode;
        if (w0 == 0x3F800000u) {
            mode = 2;                       // float32 mask (1.0f / 0.0f)
        } else {
            // distinguish int32 (every word in {0,1}) from byte-packed bool
            mode = 1;
            #pragma unroll 8
            for (int k = 0; k < 256; k++) {
                unsigned int w = objraw[k];
                if (w > 1u) { mode = 0; break; }   // packed bytes -> word like 0x00010001
            }
        }
        g_mode = mode;
    }
}

__device__ __forceinline__ float iou_vs_tgt(float cx, float cy, float w, float h,
                                            float tcx, float tcy, float tw, float th) {
    const float inv_s = 1.0f / (float)SGRID;
    float ax0 = cx * inv_s - 0.5f * w, ay0 = cy * inv_s - 0.5f * h;
    float ax1 = cx * inv_s + 0.5f * w, ay1 = cy * inv_s + 0.5f * h;
    float bx0 = tcx * inv_s - 0.5f * tw, by0 = tcy * inv_s - 0.5f * th;
    float bx1 = tcx * inv_s + 0.5f * tw, by1 = tcy * inv_s + 0.5f * th;
    float iw = fmaxf(fminf(ax1, bx1) - fmaxf(ax0, bx0), 0.0f);
    float ih = fmaxf(fminf(ay1, by1) - fmaxf(ay0, by0), 0.0f);
    float inter = iw * ih;
    float a1 = (ax1 - ax0) * (ay1 - ay0);
    float a2 = (bx1 - bx0) * (by1 - by0);
    return inter / (a1 + a2 - inter);
}

__global__ __launch_bounds__(TPB)
void yolo_reduce_kernel(const float* __restrict__ pred,
                        const float* __restrict__ tboxes,
                        const float* __restrict__ tcls,
                        const void* __restrict__ objmap) {
    __shared__ float sp[TPB * 31];   // pred staged, stride 31 (conflict-free)
    __shared__ float sc[TPB * 21];   // tcls staged, stride 21 (conflict-free)
    __shared__ float wred[TPB / 32][9];
    __shared__ int   wmax[TPB / 32];

    const int base = blockIdx.x * TPB;
    const int tid = threadIdx.x;

    // coalesced cooperative fill of pred (30 ch/cell) and tcls (20 ch/cell)
    {
        const float* src = pred + (size_t)base * 30;
        #pragma unroll 4
        for (int k = tid; k < TPB * 30; k += TPB)
            sp[(k / 30) * 31 + (k % 30)] = src[k];
        const float* csrc = tcls + (size_t)base * 20;
        #pragma unroll 4
        for (int k = tid; k < TPB * 20; k += TPB)
            sc[(k / 20) * 21 + (k % 20)] = csrc[k];
    }
    __syncthreads();

    const int i = base + tid;  // CELLS % TPB == 0, no tail
    const float* p = &sp[tid * 31];
    const float* c = &sc[tid * 21];

    float v[9];
    #pragma unroll
    for (int k = 0; k < 9; k++) v[k] = 0.0f;
    int myidx = -1;

    // cls loss (all cells)
    float cls = 0.0f;
    #pragma unroll
    for (int k = 0; k < 20; k++) {
        float d = p[10 + k] - c[k];
        cls = fmaf(d, d, cls);
    }
    v[0] = cls;

    const float4 tb = __ldg(((const float4*)tboxes) + i);  // 16B-aligned, coalesced

    const int mode = g_mode;   // uniform
    bool obj;
    if (mode == 0)      obj = ((const unsigned char*)objmap)[i] != 0;
    else if (mode == 1) obj = ((const int*)objmap)[i] != 0;
    else                obj = ((const float*)objmap)[i] != 0.0f;

    const float conf0 = p[4], conf1 = p[9];

    if (obj) {
        myidx = i;
        v[8] = 1.0f;
        float sw = sqrtf(tb.z), sh = sqrtf(tb.w);
        float d0x = p[0] - tb.x, d0y = p[1] - tb.y;
        float d0w = sqrtf(p[2]) - sw, d0h = sqrtf(p[3]) - sh;
        v[2] = d0x * d0x + d0y * d0y + d0w * d0w + d0h * d0h;
        float d1x = p[5] - tb.x, d1y = p[6] - tb.y;
        float d1w = sqrtf(p[7]) - sw, d1h = sqrtf(p[8]) - sh;
        v[3] = d1x * d1x + d1y * d1y + d1w * d1w + d1h * d1h;
        v[4] = conf0; v[5] = conf0 * conf0;
        v[6] = conf1; v[7] = conf1 * conf1;
    } else {
        v[1] = conf0 * conf0;
    }

    // warp reduce
    #pragma unroll
    for (int off = 16; off > 0; off >>= 1) {
        #pragma unroll
        for (int k = 0; k < 9; k++)
            v[k] += __shfl_down_sync(0xFFFFFFFFu, v[k], off);
        myidx = max(myidx, __shfl_down_sync(0xFFFFFFFFu, myidx, off));
    }
    const int warp = tid >> 5, lane = tid & 31;
    if (lane == 0) {
        #pragma unroll
        for (int k = 0; k < 9; k++) wred[warp][k] = v[k];
        wmax[warp] = myidx;
    }
    __syncthreads();

    if (warp == 0) {
        constexpr int NW = TPB / 32;
        float s[9];
        int mi;
        if (lane < NW) {
            #pragma unroll
            for (int k = 0; k < 9; k++) s[k] = wred[lane][k];
            mi = wmax[lane];
        } else {
            #pragma unroll
            for (int k = 0; k < 9; k++) s[k] = 0.0f;
            mi = -1;
        }
        #pragma unroll
        for (int off = NW / 2; off > 0; off >>= 1) {
            #pragma unroll
            for (int k = 0; k < 9; k++)
                s[k] += __shfl_down_sync(0xFFFFFFFFu, s[k], off);
            mi = max(mi, __shfl_down_sync(0xFFFFFFFFu, mi, off));
        }
        if (lane == 0) {
            #pragma unroll
            for (int k = 0; k < 9; k++)
                atomicAdd(&g_acc[k], (double)s[k]);
            atomicMax(&g_idx, mi);
        }
    }
}

__global__ void yolo_finalize_kernel(const float* __restrict__ pred,
                                     const float* __restrict__ tboxes,
                                     float* __restrict__ out) {
    const int idx = g_idx;
    const float* p = pred + (size_t)idx * 30;
    const float4 tb = ((const float4*)tboxes)[idx];

    float iou0 = iou_vs_tgt(p[0], p[1], p[2], p[3], tb.x, tb.y, tb.z, tb.w);
    float iou1 = iou_vs_tgt(p[5], p[6], p[7], p[8], tb.x, tb.y, tb.z, tb.w);
    bool m = iou0 > iou1;
    double cbi = (double)(m ? iou0 : iou1);

    double cls    = g_acc[0];
    double noobj  = (double)L_NOOBJ * 2.0 * g_acc[1];
    double reg    = (double)L_COORD * (m ? g_acc[2] : g_acc[3]);
    double csum   = m ? g_acc[4] : g_acc[6];
    double csq    = m ? g_acc[5] : g_acc[7];
    double nobj   = g_acc[8];
    double contain = csq - 2.0 * cbi * csum + cbi * cbi * nobj;

    double total = cls + noobj + reg + contain;
    const double invN = 1.0 / (double)NBATCH;
    out[0] = (float)(total   * invN);
    out[1] = (float)(reg     * invN);
    out[2] = (float)(contain * invN);
    out[3] = (float)(noobj   * invN);
    out[4] = (float)(cls     * invN);
}

extern "C" void kernel_launch(void* const* d_in, const int* in_sizes, int n_in,
                              void* d_out, int out_size) {
    const float* pred   = (const float*)d_in[0];
    const float* tboxes = (const float*)d_in[1];
    const float* tcls   = (const float*)d_in[2];
    const void*  objmap = (const void*)d_in[3];
    float* out = (float*)d_out;

    yolo_init_kernel<<<1, 32>>>((const unsigned int*)objmap);
    yolo_reduce_kernel<<<CELLS / TPB, TPB>>>(pred, tboxes, tcls, objmap);
    yolo_finalize_kernel<<<1, 1>>>(pred, tboxes, out);
}

// round 3
// speedup vs baseline: 1.1222x; 1.1222x over previous
#include <cuda_runtime.h>
#include <math.h>

#define SGRID 14
#define L_COORD 5.0
#define L_NOOBJ 0.5
#define NBATCH 4096
#define CELLS (NBATCH * SGRID * SGRID)  /* 802816 */
#define TPB 128
#define NBLK (CELLS / TPB)              /* 6272 */

// per-block partials: 0=cls 1=noobj 2=reg0 3=reg1 4=c0sum 5=c0sq 6=c1sum 7=c1sq 8=nobj
__device__ float g_part[NBLK][9];
__device__ int   g_pidx[NBLK];
__device__ unsigned int g_ticket;   // zero-init; last block resets to 0

__device__ __forceinline__ float iou_vs_tgt(float cx, float cy, float w, float h,
                                            float tcx, float tcy, float tw, float th) {
    const float inv_s = 1.0f / (float)SGRID;
    float ax0 = cx * inv_s - 0.5f * w, ay0 = cy * inv_s - 0.5f * h;
    float ax1 = cx * inv_s + 0.5f * w, ay1 = cy * inv_s + 0.5f * h;
    float bx0 = tcx * inv_s - 0.5f * tw, by0 = tcy * inv_s - 0.5f * th;
    float bx1 = tcx * inv_s + 0.5f * tw, by1 = tcy * inv_s + 0.5f * th;
    float iw = fmaxf(fminf(ax1, bx1) - fmaxf(ax0, bx0), 0.0f);
    float ih = fmaxf(fminf(ay1, by1) - fmaxf(ay0, by0), 0.0f);
    float inter = iw * ih;
    float a1 = (ax1 - ax0) * (ay1 - ay0);
    float a2 = (bx1 - bx0) * (by1 - by0);
    return inter / (a1 + a2 - inter);
}

__global__ __launch_bounds__(TPB)
void yolo_fused_kernel(const float* __restrict__ pred,
                       const float* __restrict__ tboxes,
                       const float* __restrict__ tcls,
                       const unsigned int* __restrict__ objraw,
                       float* __restrict__ out) {
    __shared__ float sp[TPB * 30];
    __shared__ float sc[TPB * 20];
    __shared__ float wred[TPB / 32][9];
    __shared__ int   wmax[TPB / 32];
    __shared__ int   s_last;

    const int tid = threadIdx.x;
    const int base = blockIdx.x * TPB;

    // ---- mask dtype probe (first 512B of mask, L2-resident for all blocks) ----
    const unsigned int w0 = objraw[0];            // cell(0,0,0) forced True
    const unsigned int wt = objraw[tid];          // 128 words, >=512B in every mode
    const bool isF32 = (w0 == 0x3F800000u);
    const int anyGT = __syncthreads_or((wt > 1u) && !isF32);
    const int mode = isF32 ? 2 : (anyGT ? 0 : 1); // 2=f32, 0=packed u8, 1=i32

    // ---- coalesced float4 staging (linear layout; no div/mod) ----
    {
        const float4* s4 = (const float4*)(pred + (size_t)base * 30);
        #pragma unroll
        for (int j = tid; j < TPB * 30 / 4; j += TPB)
            ((float4*)sp)[j] = s4[j];
        const float4* c4 = (const float4*)(tcls + (size_t)base * 20);
        #pragma unroll
        for (int j = tid; j < TPB * 20 / 4; j += TPB)
            ((float4*)sc)[j] = c4[j];
    }
    __syncthreads();

    const int i = base + tid;
    const float* p = &sp[tid * 30];
    const float* c = &sc[tid * 20];

    float v[9];
    #pragma unroll
    for (int k = 0; k < 9; k++) v[k] = 0.0f;
    int myidx = -1;

    float cls = 0.0f;
    #pragma unroll
    for (int k = 0; k < 20; k++) {
        float d = p[10 + k] - c[k];
        cls = fmaf(d, d, cls);
    }
    v[0] = cls;

    const float4 tb = __ldg(((const float4*)tboxes) + i);

    bool obj;
    if (mode == 1)      obj = ((const int*)objraw)[i] != 0;
    else if (mode == 2) obj = ((const float*)objraw)[i] != 0.0f;
    else                obj = ((const unsigned char*)objraw)[i] != 0;

    const float conf0 = p[4], conf1 = p[9];
    if (obj) {
        myidx = i;
        v[8] = 1.0f;
        float sw = sqrtf(tb.z), sh = sqrtf(tb.w);
        float d0x = p[0] - tb.x, d0y = p[1] - tb.y;
        float d0w = sqrtf(p[2]) - sw, d0h = sqrtf(p[3]) - sh;
        v[2] = d0x * d0x + d0y * d0y + d0w * d0w + d0h * d0h;
        float d1x = p[5] - tb.x, d1y = p[6] - tb.y;
        float d1w = sqrtf(p[7]) - sw, d1h = sqrtf(p[8]) - sh;
        v[3] = d1x * d1x + d1y * d1y + d1w * d1w + d1h * d1h;
        v[4] = conf0; v[5] = conf0 * conf0;
        v[6] = conf1; v[7] = conf1 * conf1;
    } else {
        v[1] = conf0 * conf0;
    }

    // ---- block reduce ----
    #pragma unroll
    for (int off = 16; off > 0; off >>= 1) {
        #pragma unroll
        for (int k = 0; k < 9; k++)
            v[k] += __shfl_down_sync(0xFFFFFFFFu, v[k], off);
        myidx = max(myidx, __shfl_down_sync(0xFFFFFFFFu, myidx, off));
    }
    const int warp = tid >> 5, lane = tid & 31;
    if (lane == 0) {
        #pragma unroll
        for (int k = 0; k < 9; k++) wred[warp][k] = v[k];
        wmax[warp] = myidx;
    }
    __syncthreads();

    if (tid == 0) {
        float s[9];
        int mi = -1;
        #pragma unroll
        for (int k = 0; k < 9; k++) s[k] = 0.0f;
        #pragma unroll
        for (int wq = 0; wq < TPB / 32; wq++) {
            #pragma unroll
            for (int k = 0; k < 9; k++) s[k] += wred[wq][k];
            mi = max(mi, wmax[wq]);
        }
        #pragma unroll
        for (int k = 0; k < 9; k++) g_part[blockIdx.x][k] = s[k];
        g_pidx[blockIdx.x] = mi;
        __threadfence();
        unsigned int t = atomicAdd(&g_ticket, 1u);
        s_last = (t == (unsigned int)(gridDim.x - 1)) ? 1 : 0;
    }
    __syncthreads();

    // ---- last block: final reduction + output ----
    if (s_last) {
        double a[9];
        #pragma unroll
        for (int k = 0; k < 9; k++) a[k] = 0.0;
        int mi = -1;
        for (int b = tid; b < NBLK; b += TPB) {
            #pragma unroll
            for (int k = 0; k < 9; k++) a[k] += (double)g_part[b][k];
            mi = max(mi, g_pidx[b]);
        }
        #pragma unroll
        for (int off = 16; off > 0; off >>= 1) {
            #pragma unroll
            for (int k = 0; k < 9; k++)
                a[k] += __shfl_down_sync(0xFFFFFFFFu, a[k], off);
            mi = max(mi, __shfl_down_sync(0xFFFFFFFFu, mi, off));
        }
        __shared__ double dred[TPB / 32][9];
        __shared__ int    dmax[TPB / 32];
        if (lane == 0) {
            #pragma unroll
            for (int k = 0; k < 9; k++) dred[warp][k] = a[k];
            dmax[warp] = mi;
        }
        __syncthreads();
        if (tid == 0) {
            double t9[9];
            int idx = -1;
            #pragma unroll
            for (int k = 0; k < 9; k++) t9[k] = 0.0;
            #pragma unroll
            for (int wq = 0; wq < TPB / 32; wq++) {
                #pragma unroll
                for (int k = 0; k < 9; k++) t9[k] += dred[wq][k];
                idx = max(idx, dmax[wq]);
            }

            const float* pp = pred + (size_t)idx * 30;
            const float4 tbx = ((const float4*)tboxes)[idx];
            float iou0 = iou_vs_tgt(pp[0], pp[1], pp[2], pp[3], tbx.x, tbx.y, tbx.z, tbx.w);
            float iou1 = iou_vs_tgt(pp[5], pp[6], pp[7], pp[8], tbx.x, tbx.y, tbx.z, tbx.w);
            bool m = iou0 > iou1;
            double cbi = (double)(m ? iou0 : iou1);

            double clsL    = t9[0];
            double noobj   = L_NOOBJ * 2.0 * t9[1];
            double reg     = L_COORD * (m ? t9[2] : t9[3]);
            double csum    = m ? t9[4] : t9[6];
            double csq     = m ? t9[5] : t9[7];
            double nobj    = t9[8];
            double contain = csq - 2.0 * cbi * csum + cbi * cbi * nobj;
            double total   = clsL + noobj + reg + contain;
            const double invN = 1.0 / (double)NBATCH;
            out[0] = (float)(total   * invN);
            out[1] = (float)(reg     * invN);
            out[2] = (float)(contain * invN);
            out[3] = (float)(noobj   * invN);
            out[4] = (float)(clsL    * invN);

            g_ticket = 0;   // reset for next (graph-replayed) call
        }
    }
}

extern "C" void kernel_launch(void* const* d_in, const int* in_sizes, int n_in,
                              void* d_out, int out_size) {
    const float* pred   = (const float*)d_in[0];
    const float* tboxes = (const float*)d_in[1];
    const float* tcls   = (const float*)d_in[2];
    const unsigned int* objraw = (const unsigned int*)d_in[3];
    float* out = (float*)d_out;

    yolo_fused_kernel<<<NBLK, TPB>>>(pred, tboxes, tcls, objraw, out);
}

// round 4
// speedup vs baseline: 1.8706x; 1.6669x over previous
#include <cuda_runtime.h>
#include <math.h>
#include <stdint.h>

#define SGRID 14
#define NBATCH 4096
#define CELLS 802816              /* 4096 * 14 * 14 */
#define TPB 128
#define TILE 128                  /* cells per tile */
#define NT (CELLS / TILE)         /* 6272 tiles */
#define GRID 592                  /* 4 blocks/SM * 148 SMs = one wave */
#define DEPTH 3
#define PRED_TB (TILE * 30 * 4)   /* 15360 B per pred tile */

// per-block partials: 0=cls 1=noobj 2=reg0 3=reg1 4=c0sum 5=c0sq 6=c1sum 7=c1sq 8=nobj
__device__ float g_part[GRID][9];
__device__ int   g_pidx[GRID];
__device__ unsigned int g_ticket;   // zero-init; last block resets to 0

__device__ __forceinline__ uint32_t s2u(const void* p) {
    return (uint32_t)__cvta_generic_to_shared(p);
}
__device__ __forceinline__ void mbar_init(uint32_t a, uint32_t n) {
    asm volatile("mbarrier.init.shared.b64 [%0], %1;" :: "r"(a), "r"(n) : "memory");
}
__device__ __forceinline__ void mbar_arrive(uint32_t a) {
    asm volatile("mbarrier.arrive.shared.b64 _, [%0];" :: "r"(a) : "memory");
}
__device__ __forceinline__ void mbar_arrive_tx(uint32_t a, uint32_t tx) {
    asm volatile("mbarrier.arrive.expect_tx.shared.b64 _, [%0], %1;" :: "r"(a), "r"(tx) : "memory");
}
__device__ __forceinline__ void mbar_wait(uint32_t a, uint32_t ph) {
    asm volatile(
        "{\n\t.reg .pred P;\n"
        "WAIT_%=:\n\t"
        "mbarrier.try_wait.parity.acquire.cta.shared::cta.b64 P, [%0], %1, 0x989680;\n\t"
        "@P bra DONE_%=;\n\t"
        "bra WAIT_%=;\n"
        "DONE_%=:\n\t}"
        :: "r"(a), "r"(ph) : "memory");
}
__device__ __forceinline__ void bulk_g2s(uint32_t dst, const void* src, uint32_t bytes, uint32_t mbar) {
    asm volatile(
        "cp.async.bulk.shared::cluster.global.mbarrier::complete_tx::bytes [%0], [%1], %2, [%3];"
        :: "r"(dst), "l"(src), "r"(bytes), "r"(mbar) : "memory");
}

__device__ __forceinline__ float iou_vs_tgt(float cx, float cy, float w, float h,
                                            float tcx, float tcy, float tw, float th) {
    const float inv_s = 1.0f / (float)SGRID;
    float ax0 = cx * inv_s - 0.5f * w, ay0 = cy * inv_s - 0.5f * h;
    float ax1 = cx * inv_s + 0.5f * w, ay1 = cy * inv_s + 0.5f * h;
    float bx0 = tcx * inv_s - 0.5f * tw, by0 = tcy * inv_s - 0.5f * th;
    float bx1 = tcx * inv_s + 0.5f * tw, by1 = tcy * inv_s + 0.5f * th;
    float iw = fmaxf(fminf(ax1, bx1) - fmaxf(ax0, bx0), 0.0f);
    float ih = fmaxf(fminf(ay1, by1) - fmaxf(ay0, by0), 0.0f);
    float inter = iw * ih;
    float a1 = (ax1 - ax0) * (ay1 - ay0);
    float a2 = (bx1 - bx0) * (by1 - by0);
    return inter / (a1 + a2 - inter);
}

__global__ __launch_bounds__(TPB)
void yolo_pipe_kernel(const float* __restrict__ pred,
                      const float* __restrict__ tboxes,
                      const float* __restrict__ tcls,
                      const unsigned int* __restrict__ objraw,
                      float* __restrict__ out) {
    __shared__ float sp[DEPTH][TILE * 30];          // 46080 B
    __shared__ unsigned long long bar[2 * DEPTH];   // full[0..2], empty[0..2]
    __shared__ float wred[TPB / 32][9];
    __shared__ int   wmax[TPB / 32];
    __shared__ int   s_last;

    const int tid = threadIdx.x;
    const int b = blockIdx.x;
    const int ntiles = (NT - b + GRID - 1) / GRID;

    // ---- mask dtype probe (first 512B, L2-resident) ----
    const unsigned int w0 = objraw[0];            // cell(0,0,0) forced True
    const unsigned int wt = objraw[tid];
    const bool isF32 = (w0 == 0x3F800000u);
    const int anyGT = __syncthreads_or((wt > 1u) && !isF32);
    const int mode = isF32 ? 2 : (anyGT ? 0 : 1); // 2=f32, 0=packed u8, 1=i32

    uint32_t fullA[DEPTH], emptyA[DEPTH], spA[DEPTH];
    #pragma unroll
    for (int d = 0; d < DEPTH; d++) {
        fullA[d]  = s2u(&bar[d]);
        emptyA[d] = s2u(&bar[DEPTH + d]);
        spA[d]    = s2u(&sp[d][0]);
    }

    if (tid == 0) {
        #pragma unroll
        for (int d = 0; d < DEPTH; d++) {
            mbar_init(fullA[d], 1);
            mbar_init(emptyA[d], TPB);
        }
    }
    __syncthreads();

    // ---- prologue: issue first DEPTH tiles ----
    if (tid == 0) {
        int np = ntiles < DEPTH ? ntiles : DEPTH;
        for (int d = 0; d < np; d++) {
            int tile = b + GRID * d;
            mbar_arrive_tx(fullA[d], PRED_TB);
            bulk_g2s(spA[d], pred + (size_t)tile * (TILE * 30), PRED_TB, fullA[d]);
        }
    }

    unsigned int fph = 0, eph = 0;   // per-stage phase bits
    float v[9];
    #pragma unroll
    for (int k = 0; k < 9; k++) v[k] = 0.0f;
    int myidx = -1;

    for (int j = 0; j < ntiles; j++) {
        const int s = j % DEPTH;
        mbar_wait(fullA[s], (fph >> s) & 1u);
        fph ^= 1u << s;

        const int tile = b + GRID * j;
        const int ci = tile * TILE + tid;
        const float* p = &sp[s][tid * 30];

        // cls: pred ch10..29 from smem vs tcls via direct float4 LDG
        const float4* c4 = ((const float4*)tcls) + (size_t)ci * 5;
        float cls = 0.0f;
        #pragma unroll
        for (int q = 0; q < 5; q++) {
            float4 c = __ldg(c4 + q);
            float d0 = p[10 + 4 * q + 0] - c.x;
            float d1 = p[10 + 4 * q + 1] - c.y;
            float d2 = p[10 + 4 * q + 2] - c.z;
            float d3 = p[10 + 4 * q + 3] - c.w;
            cls = fmaf(d0, d0, cls);
            cls = fmaf(d1, d1, cls);
            cls = fmaf(d2, d2, cls);
            cls = fmaf(d3, d3, cls);
        }
        v[0] += cls;

        const float4 tb = __ldg(((const float4*)tboxes) + ci);
        bool obj;
        if (mode == 1)      obj = ((const int*)objraw)[ci] != 0;
        else if (mode == 2) obj = ((const float*)objraw)[ci] != 0.0f;
        else                obj = ((const unsigned char*)objraw)[ci] != 0;

        const float conf0 = p[4], conf1 = p[9];
        if (obj) {
            myidx = max(myidx, ci);
            v[8] += 1.0f;
            float sw = sqrtf(tb.z), sh = sqrtf(tb.w);
            float d0x = p[0] - tb.x, d0y = p[1] - tb.y;
            float d0w = sqrtf(p[2]) - sw, d0h = sqrtf(p[3]) - sh;
            v[2] += d0x * d0x + d0y * d0y + d0w * d0w + d0h * d0h;
            float d1x = p[5] - tb.x, d1y = p[6] - tb.y;
            float d1w = sqrtf(p[7]) - sw, d1h = sqrtf(p[8]) - sh;
            v[3] += d1x * d1x + d1y * d1y + d1w * d1w + d1h * d1h;
            v[4] += conf0; v[5] += conf0 * conf0;
            v[6] += conf1; v[7] += conf1 * conf1;
        } else {
            v[1] += conf0 * conf0;
        }

        mbar_arrive(emptyA[s]);

        // producer: refill this stage with tile j+DEPTH
        if (tid == 0 && j + DEPTH < ntiles) {
            mbar_wait(emptyA[s], (eph >> s) & 1u);
            eph ^= 1u << s;
            int t2 = b + GRID * (j + DEPTH);
            mbar_arrive_tx(fullA[s], PRED_TB);
            bulk_g2s(spA[s], pred + (size_t)t2 * (TILE * 30), PRED_TB, fullA[s]);
        }
    }

    // ---- block reduce ----
    #pragma unroll
    for (int off = 16; off > 0; off >>= 1) {
        #pragma unroll
        for (int k = 0; k < 9; k++)
            v[k] += __shfl_down_sync(0xFFFFFFFFu, v[k], off);
        myidx = max(myidx, __shfl_down_sync(0xFFFFFFFFu, myidx, off));
    }
    const int warp = tid >> 5, lane = tid & 31;
    if (lane == 0) {
        #pragma unroll
        for (int k = 0; k < 9; k++) wred[warp][k] = v[k];
        wmax[warp] = myidx;
    }
    __syncthreads();

    if (tid == 0) {
        float s9[9];
        int mi = -1;
        #pragma unroll
        for (int k = 0; k < 9; k++) s9[k] = 0.0f;
        #pragma unroll
        for (int wq = 0; wq < TPB / 32; wq++) {
            #pragma unroll
            for (int k = 0; k < 9; k++) s9[k] += wred[wq][k];
            mi = max(mi, wmax[wq]);
        }
        #pragma unroll
        for (int k = 0; k < 9; k++) g_part[b][k] = s9[k];
        g_pidx[b] = mi;
        __threadfence();
        unsigned int t = atomicAdd(&g_ticket, 1u);
        s_last = (t == (unsigned int)(GRID - 1)) ? 1 : 0;
    }
    __syncthreads();

    // ---- last block: final reduction + output ----
    if (s_last) {
        double a[9];
        #pragma unroll
        for (int k = 0; k < 9; k++) a[k] = 0.0;
        int mi = -1;
        for (int q = tid; q < GRID; q += TPB) {
            #pragma unroll
            for (int k = 0; k < 9; k++) a[k] += (double)g_part[q][k];
            mi = max(mi, g_pidx[q]);
        }
        #pragma unroll
        for (int off = 16; off > 0; off >>= 1) {
            #pragma unroll
            for (int k = 0; k < 9; k++)
                a[k] += __shfl_down_sync(0xFFFFFFFFu, a[k], off);
            mi = max(mi, __shfl_down_sync(0xFFFFFFFFu, mi, off));
        }
        __shared__ double dred[TPB / 32][9];
        __shared__ int    dmax[TPB / 32];
        if (lane == 0) {
            #pragma unroll
            for (int k = 0; k < 9; k++) dred[warp][k] = a[k];
            dmax[warp] = mi;
        }
        __syncthreads();
        if (tid == 0) {
            double t9[9];
            int idx = -1;
            #pragma unroll
            for (int k = 0; k < 9; k++) t9[k] = 0.0;
            #pragma unroll
            for (int wq = 0; wq < TPB / 32; wq++) {
                #pragma unroll
                for (int k = 0; k < 9; k++) t9[k] += dred[wq][k];
                idx = max(idx, dmax[wq]);
            }

            const float* pp = pred + (size_t)idx * 30;
            const float4 tbx = ((const float4*)tboxes)[idx];
            float iou0 = iou_vs_tgt(pp[0], pp[1], pp[2], pp[3], tbx.x, tbx.y, tbx.z, tbx.w);
            float iou1 = iou_vs_tgt(pp[5], pp[6], pp[7], pp[8], tbx.x, tbx.y, tbx.z, tbx.w);
            bool m = iou0 > iou1;
            double cbi = (double)(m ? iou0 : iou1);

            double clsL    = t9[0];
            double noobj   = 0.5 * 2.0 * t9[1];
            double reg     = 5.0 * (m ? t9[2] : t9[3]);
            double csum    = m ? t9[4] : t9[6];
            double csq     = m ? t9[5] : t9[7];
            double nobj    = t9[8];
            double contain = csq - 2.0 * cbi * csum + cbi * cbi * nobj;
            double total   = clsL + noobj + reg + contain;
            const double invN = 1.0 / (double)NBATCH;
            out[0] = (float)(total   * invN);
            out[1] = (float)(reg     * invN);
            out[2] = (float)(contain * invN);
            out[3] = (float)(noobj   * invN);
            out[4] = (float)(clsL    * invN);

            g_ticket = 0;   // reset for graph replay
        }
    }
}

extern "C" void kernel_launch(void* const* d_in, const int* in_sizes, int n_in,
                              void* d_out, int out_size) {
    const float* pred   = (const float*)d_in[0];
    const float* tboxes = (const float*)d_in[1];
    const float* tcls   = (const float*)d_in[2];
    const unsigned int* objraw = (const unsigned int*)d_in[3];
    float* out = (float*)d_out;

    yolo_pipe_kernel<<<GRID, TPB>>>(pred, tboxes, tcls, objraw, out);
}

// round 5
// speedup vs baseline: 2.1836x; 1.1673x over previous
#include <cuda_runtime.h>
#include <math.h>
#include <stdint.h>

#define SGRID 14
#define NBATCH 4096
#define CELLS 802816              /* 4096 * 14 * 14 */
#define TPB 128
#define TILE 128                  /* cells per tile */
#define NT (CELLS / TILE)         /* 6272 tiles */
#define GRID 296                  /* 2 blocks/SM * 148 SMs = one wave */
#define DEPTH 3

#define PRED_TB (TILE * 30 * 4)   /* 15360 */
#define CLS_TB  (TILE * 20 * 4)   /* 10240 */
#define BOX_TB  (TILE * 4 * 4)    /*  2048 */
#define MASK_MAX 512              /* i32/f32 mask bytes per tile; u8 = 128 */
#define STAGE_B (PRED_TB + CLS_TB + BOX_TB + MASK_MAX)   /* 28160 */
#define OFF_PRED 0
#define OFF_CLS  PRED_TB
#define OFF_BOX  (PRED_TB + CLS_TB)
#define OFF_MASK (PRED_TB + CLS_TB + BOX_TB)

// per-block partials: 0=cls 1=noobj 2=reg0 3=reg1 4=c0sum 5=c0sq 6=c1sum 7=c1sq 8=nobj
__device__ float g_part[GRID][9];
__device__ int   g_pidx[GRID];
__device__ unsigned int g_ticket;   // zero-init; last block resets to 0

__device__ __forceinline__ uint32_t s2u(const void* p) {
    return (uint32_t)__cvta_generic_to_shared(p);
}
__device__ __forceinline__ void mbar_init(uint32_t a, uint32_t n) {
    asm volatile("mbarrier.init.shared.b64 [%0], %1;" :: "r"(a), "r"(n) : "memory");
}
__device__ __forceinline__ void mbar_arrive(uint32_t a) {
    asm volatile("mbarrier.arrive.shared.b64 _, [%0];" :: "r"(a) : "memory");
}
__device__ __forceinline__ void mbar_arrive_tx(uint32_t a, uint32_t tx) {
    asm volatile("mbarrier.arrive.expect_tx.shared.b64 _, [%0], %1;" :: "r"(a), "r"(tx) : "memory");
}
__device__ __forceinline__ void mbar_wait(uint32_t a, uint32_t ph) {
    asm volatile(
        "{\n\t.reg .pred P;\n"
        "WAIT_%=:\n\t"
        "mbarrier.try_wait.parity.acquire.cta.shared::cta.b64 P, [%0], %1, 0x989680;\n\t"
        "@P bra DONE_%=;\n\t"
        "bra WAIT_%=;\n"
        "DONE_%=:\n\t}"
        :: "r"(a), "r"(ph) : "memory");
}
__device__ __forceinline__ void bulk_g2s(uint32_t dst, const void* src, uint32_t bytes, uint32_t mbar) {
    asm volatile(
        "cp.async.bulk.shared::cluster.global.mbarrier::complete_tx::bytes [%0], [%1], %2, [%3];"
        :: "r"(dst), "l"(src), "r"(bytes), "r"(mbar) : "memory");
}

__device__ __forceinline__ float iou_vs_tgt(float cx, float cy, float w, float h,
                                            float tcx, float tcy, float tw, float th) {
    const float inv_s = 1.0f / (float)SGRID;
    float ax0 = cx * inv_s - 0.5f * w, ay0 = cy * inv_s - 0.5f * h;
    float ax1 = cx * inv_s + 0.5f * w, ay1 = cy * inv_s + 0.5f * h;
    float bx0 = tcx * inv_s - 0.5f * tw, by0 = tcy * inv_s - 0.5f * th;
    float bx1 = tcx * inv_s + 0.5f * tw, by1 = tcy * inv_s + 0.5f * th;
    float iw = fmaxf(fminf(ax1, bx1) - fmaxf(ax0, bx0), 0.0f);
    float ih = fmaxf(fminf(ay1, by1) - fmaxf(ay0, by0), 0.0f);
    float inter = iw * ih;
    float a1 = (ax1 - ax0) * (ay1 - ay0);
    float a2 = (bx1 - bx0) * (by1 - by0);
    return inter / (a1 + a2 - inter);
}

__global__ __launch_bounds__(TPB)
void yolo_pipe2_kernel(const float* __restrict__ pred,
                       const float* __restrict__ tboxes,
                       const float* __restrict__ tcls,
                       const unsigned int* __restrict__ objraw,
                       float* __restrict__ out) {
    extern __shared__ char dyn[];                  // DEPTH * STAGE_B
    __shared__ unsigned long long bar[2 * DEPTH];  // full[d], empty[d]
    __shared__ float wred[TPB / 32][9];
    __shared__ int   wmax[TPB / 32];
    __shared__ int   s_last;

    const int tid = threadIdx.x;
    const int b = blockIdx.x;
    const int ntiles = (NT - b + GRID - 1) / GRID;

    // ---- mask dtype probe (first 512B, L2-resident) ----
    const unsigned int w0 = objraw[0];            // cell(0,0,0) forced True
    const unsigned int wt = objraw[tid];
    const bool isF32 = (w0 == 0x3F800000u);
    const int anyGT = __syncthreads_or((wt > 1u) && !isF32);
    const int mode = isF32 ? 2 : (anyGT ? 0 : 1); // 2=f32, 0=packed u8, 1=i32
    const uint32_t mtx = (mode == 0) ? (TILE) : (TILE * 4);          // mask bytes/tile
    const uint32_t txTotal = PRED_TB + CLS_TB + BOX_TB + mtx;
    const char* maskBase = (const char*)objraw;

    uint32_t fullA[DEPTH], emptyA[DEPTH], stA[DEPTH];
    #pragma unroll
    for (int d = 0; d < DEPTH; d++) {
        fullA[d]  = s2u(&bar[d]);
        emptyA[d] = s2u(&bar[DEPTH + d]);
        stA[d]    = s2u(dyn + d * STAGE_B);
    }

    if (tid == 0) {
        #pragma unroll
        for (int d = 0; d < DEPTH; d++) {
            mbar_init(fullA[d], 1);
            mbar_init(emptyA[d], TPB);
        }
    }
    __syncthreads();

    // ---- prologue ----
    if (tid == 0) {
        int np = ntiles < DEPTH ? ntiles : DEPTH;
        for (int d = 0; d < np; d++) {
            size_t tile = (size_t)(b + GRID * d);
            mbar_arrive_tx(fullA[d], txTotal);
            bulk_g2s(stA[d] + OFF_PRED, pred   + tile * (TILE * 30), PRED_TB, fullA[d]);
            bulk_g2s(stA[d] + OFF_CLS,  tcls   + tile * (TILE * 20), CLS_TB,  fullA[d]);
            bulk_g2s(stA[d] + OFF_BOX,  tboxes + tile * (TILE * 4),  BOX_TB,  fullA[d]);
            bulk_g2s(stA[d] + OFF_MASK, maskBase + tile * mtx,       mtx,     fullA[d]);
        }
    }

    unsigned int fph = 0, eph = 0;
    float v[9];
    #pragma unroll
    for (int k = 0; k < 9; k++) v[k] = 0.0f;
    int myidx = -1;

    for (int j = 0; j < ntiles; j++) {
        const int s = j % DEPTH;
        mbar_wait(fullA[s], (fph >> s) & 1u);
        fph ^= 1u << s;

        const char* stg = dyn + s * STAGE_B;
        const float* p = (const float*)(stg + OFF_PRED) + tid * 30;
        const float4* c4 = (const float4*)(stg + OFF_CLS) + tid * 5;
        const float4 tb = ((const float4*)(stg + OFF_BOX))[tid];

        bool obj;
        if (mode == 1)      obj = ((const int*)(stg + OFF_MASK))[tid] != 0;
        else if (mode == 2) obj = ((const float*)(stg + OFF_MASK))[tid] != 0.0f;
        else                obj = ((const unsigned char*)(stg + OFF_MASK))[tid] != 0;

        float cls = 0.0f;
        #pragma unroll
        for (int q = 0; q < 5; q++) {
            float4 c = c4[q];
            float d0 = p[10 + 4 * q + 0] - c.x;
            float d1 = p[10 + 4 * q + 1] - c.y;
            float d2 = p[10 + 4 * q + 2] - c.z;
            float d3 = p[10 + 4 * q + 3] - c.w;
            cls = fmaf(d0, d0, cls);
            cls = fmaf(d1, d1, cls);
            cls = fmaf(d2, d2, cls);
            cls = fmaf(d3, d3, cls);
        }
        v[0] += cls;

        const float conf0 = p[4], conf1 = p[9];
        if (obj) {
            const int ci = (b + GRID * j) * TILE + tid;
            myidx = max(myidx, ci);
            v[8] += 1.0f;
            float sw = sqrtf(tb.z), sh = sqrtf(tb.w);
            float d0x = p[0] - tb.x, d0y = p[1] - tb.y;
            float d0w = sqrtf(p[2]) - sw, d0h = sqrtf(p[3]) - sh;
            v[2] += d0x * d0x + d0y * d0y + d0w * d0w + d0h * d0h;
            float d1x = p[5] - tb.x, d1y = p[6] - tb.y;
            float d1w = sqrtf(p[7]) - sw, d1h = sqrtf(p[8]) - sh;
            v[3] += d1x * d1x + d1y * d1y + d1w * d1w + d1h * d1h;
            v[4] += conf0; v[5] += conf0 * conf0;
            v[6] += conf1; v[7] += conf1 * conf1;
        } else {
            v[1] += conf0 * conf0;
        }

        mbar_arrive(emptyA[s]);

        if (tid == 0 && j + DEPTH < ntiles) {
            mbar_wait(emptyA[s], (eph >> s) & 1u);
            eph ^= 1u << s;
            size_t t2 = (size_t)(b + GRID * (j + DEPTH));
            mbar_arrive_tx(fullA[s], txTotal);
            bulk_g2s(stA[s] + OFF_PRED, pred   + t2 * (TILE * 30), PRED_TB, fullA[s]);
            bulk_g2s(stA[s] + OFF_CLS,  tcls   + t2 * (TILE * 20), CLS_TB,  fullA[s]);
            bulk_g2s(stA[s] + OFF_BOX,  tboxes + t2 * (TILE * 4),  BOX_TB,  fullA[s]);
            bulk_g2s(stA[s] + OFF_MASK, maskBase + t2 * mtx,       mtx,     fullA[s]);
        }
    }

    // ---- block reduce ----
    #pragma unroll
    for (int off = 16; off > 0; off >>= 1) {
        #pragma unroll
        for (int k = 0; k < 9; k++)
            v[k] += __shfl_down_sync(0xFFFFFFFFu, v[k], off);
        myidx = max(myidx, __shfl_down_sync(0xFFFFFFFFu, myidx, off));
    }
    const int warp = tid >> 5, lane = tid & 31;
    if (lane == 0) {
        #pragma unroll
        for (int k = 0; k < 9; k++) wred[warp][k] = v[k];
        wmax[warp] = myidx;
    }
    __syncthreads();

    if (tid == 0) {
        float s9[9];
        int mi = -1;
        #pragma unroll
        for (int k = 0; k < 9; k++) s9[k] = 0.0f;
        #pragma unroll
        for (int wq = 0; wq < TPB / 32; wq++) {
            #pragma unroll
            for (int k = 0; k < 9; k++) s9[k] += wred[wq][k];
            mi = max(mi, wmax[wq]);
        }
        #pragma unroll
        for (int k = 0; k < 9; k++) g_part[b][k] = s9[k];
        g_pidx[b] = mi;
        __threadfence();
        unsigned int t = atomicAdd(&g_ticket, 1u);
        s_last = (t == (unsigned int)(GRID - 1)) ? 1 : 0;
    }
    __syncthreads();

    // ---- last block: final reduction + output ----
    if (s_last) {
        double a[9];
        #pragma unroll
        for (int k = 0; k < 9; k++) a[k] = 0.0;
        int mi = -1;
        for (int q = tid; q < GRID; q += TPB) {
            #pragma unroll
            for (int k = 0; k < 9; k++) a[k] += (double)g_part[q][k];
            mi = max(mi, g_pidx[q]);
        }
        #pragma unroll
        for (int off = 16; off > 0; off >>= 1) {
            #pragma unroll
            for (int k = 0; k < 9; k++)
                a[k] += __shfl_down_sync(0xFFFFFFFFu, a[k], off);
            mi = max(mi, __shfl_down_sync(0xFFFFFFFFu, mi, off));
        }
        __shared__ double dred[TPB / 32][9];
        __shared__ int    dmax[TPB / 32];
        if (lane == 0) {
            #pragma unroll
            for (int k = 0; k < 9; k++) dred[warp][k] = a[k];
            dmax[warp] = mi;
        }
        __syncthreads();
        if (tid == 0) {
            double t9[9];
            int idx = -1;
            #pragma unroll
            for (int k = 0; k < 9; k++) t9[k] = 0.0;
            #pragma unroll
            for (int wq = 0; wq < TPB / 32; wq++) {
                #pragma unroll
                for (int k = 0; k < 9; k++) t9[k] += dred[wq][k];
                idx = max(idx, dmax[wq]);
            }

            const float* pp = pred + (size_t)idx * 30;
            const float4 tbx = ((const float4*)tboxes)[idx];
            float iou0 = iou_vs_tgt(pp[0], pp[1], pp[2], pp[3], tbx.x, tbx.y, tbx.z, tbx.w);
            float iou1 = iou_vs_tgt(pp[5], pp[6], pp[7], pp[8], tbx.x, tbx.y, tbx.z, tbx.w);
            bool m = iou0 > iou1;
            double cbi = (double)(m ? iou0 : iou1);

            double clsL    = t9[0];
            double noobj   = 0.5 * 2.0 * t9[1];
            double reg     = 5.0 * (m ? t9[2] : t9[3]);
            double csum    = m ? t9[4] : t9[6];
            double csq     = m ? t9[5] : t9[7];
            double nobj    = t9[8];
            double contain = csq - 2.0 * cbi * csum + cbi * cbi * nobj;
            double total   = clsL + noobj + reg + contain;
            const double invN = 1.0 / (double)NBATCH;
            out[0] = (float)(total   * invN);
            out[1] = (float)(reg     * invN);
            out[2] = (float)(contain * invN);
            out[3] = (float)(noobj   * invN);
            out[4] = (float)(clsL    * invN);

            g_ticket = 0;   // reset for graph replay
        }
    }
}

extern "C" void kernel_launch(void* const* d_in, const int* in_sizes, int n_in,
                              void* d_out, int out_size) {
    const float* pred   = (const float*)d_in[0];
    const float* tboxes = (const float*)d_in[1];
    const float* tcls   = (const float*)d_in[2];
    const unsigned int* objraw = (const unsigned int*)d_in[3];
    float* out = (float*)d_out;

    static const int smem = DEPTH * STAGE_B;   // 84480
    cudaFuncSetAttribute(yolo_pipe2_kernel,
                         cudaFuncAttributeMaxDynamicSharedMemorySize, smem);
    yolo_pipe2_kernel<<<GRID, TPB, smem>>>(pred, tboxes, tcls, objraw, out);
}